// round 6
// baseline (speedup 1.0000x reference)
#include <cuda_runtime.h>
#include <cuda_bf16.h>
#include <math.h>
#include <stdint.h>

#define NTOK 16384
#define CDIM 8192
#define HDIM 2048
#define IDIM 8192

// Scratch (__device__ globals; allocation-free rule)
__device__ __align__(256) float g_h[(size_t)CDIM * IDIM];      // silu(g)*u
__device__ __align__(256) float g_down[(size_t)CDIM * HDIM];

// ---------------------------------------------------------------------------
// helpers (plain sm_80-era PTX only)
// ---------------------------------------------------------------------------
__device__ __forceinline__ uint32_t smem_u32(const void* p) {
    return (uint32_t)__cvta_generic_to_shared(p);
}
__device__ __forceinline__ void ldsm4(uint32_t a, uint32_t& r0, uint32_t& r1,
                                      uint32_t& r2, uint32_t& r3) {
    asm volatile("ldmatrix.sync.aligned.m8n8.x4.shared.b16 {%0,%1,%2,%3}, [%4];"
                 : "=r"(r0), "=r"(r1), "=r"(r2), "=r"(r3) : "r"(a));
}
__device__ __forceinline__ void hmma(float* c, const uint32_t* a,
                                     uint32_t b0, uint32_t b1) {
    asm volatile(
        "mma.sync.aligned.m16n8k16.row.col.f32.bf16.bf16.f32 "
        "{%0,%1,%2,%3},{%4,%5,%6,%7},{%8,%9},{%0,%1,%2,%3};"
        : "+f"(c[0]), "+f"(c[1]), "+f"(c[2]), "+f"(c[3])
        : "r"(a[0]), "r"(a[1]), "r"(a[2]), "r"(a[3]), "r"(b0), "r"(b1));
}
// fp32 -> (hi, lo) bf16 split of 4 consecutive K elements; 8B packed stores
__device__ __forceinline__ void split_store(char* hi, char* lo, float4 v) {
    __nv_bfloat162 h0 = __floats2bfloat162_rn(v.x, v.y);
    __nv_bfloat162 h1 = __floats2bfloat162_rn(v.z, v.w);
    float2 f0 = __bfloat1622float2(h0);
    float2 f1 = __bfloat1622float2(h1);
    __nv_bfloat162 l0 = __floats2bfloat162_rn(v.x - f0.x, v.y - f0.y);
    __nv_bfloat162 l1 = __floats2bfloat162_rn(v.z - f1.x, v.w - f1.y);
    uint32_t h0u = *reinterpret_cast<uint32_t*>(&h0);
    uint32_t h1u = *reinterpret_cast<uint32_t*>(&h1);
    uint32_t l0u = *reinterpret_cast<uint32_t*>(&l0);
    uint32_t l1u = *reinterpret_cast<uint32_t*>(&l1);
    *reinterpret_cast<uint2*>(hi) = make_uint2(h0u, h1u);
    *reinterpret_cast<uint2*>(lo) = make_uint2(l0u, l1u);
}
__device__ __forceinline__ float silu(float g) { return g / (1.f + expf(-g)); }

// smem rows: 32 bf16 padded to 40 (80B = 5x16B) — conflict-free ldmatrix (R3)
#define ROWB 80
// k1 sections: A_hi(128r) | A_lo | Bg_hi | Bg_lo | Bu_hi | Bu_lo
#define K1_ALO   10240
#define K1_BGHI  20480
#define K1_BGLO  30720
#define K1_BUHI  40960
#define K1_BULO  51200
#define STAGE1   61440
#define SMEM1    (2 * STAGE1)   // 120 KB
// k2 sections: A_hi(256r) | A_lo | B_hi(128r) | B_lo
#define K2_ALO   20480
#define K2_BHI   40960
#define K2_BLO   51200
#define STAGE2   61440
#define SMEM2    (2 * STAGE2)   // 120 KB

#define NC1 (HDIM / 32)   // 64 chunks
#define NC2 (IDIM / 32)   // 256 chunks

// ---------------------------------------------------------------------------
// Kernel 1: gather + dual GEMM (gate,up), 512 threads.
// Warps 0-7: gate (4m x 2n of 32x64 tiles); warps 8-15: up (same map).
// Data path identical to R3: fp32 LDG early, split_store late, double buffer.
// ---------------------------------------------------------------------------
__global__ __launch_bounds__(512, 1)
void k1_gateup(const float* __restrict__ x,
               const float* __restrict__ Wg,
               const float* __restrict__ Wu,
               const int* __restrict__ fg)
{
    extern __shared__ __align__(128) char sm[];
    const uint32_t smb = smem_u32(sm);
    const int tid  = threadIdx.x;
    const int wid  = tid >> 5;
    const int lane = tid & 31;
    const int m0 = blockIdx.x * 128;   // m fastest -> B tiles L2-resident
    const int n0 = blockIdx.y * 128;

    // staging: 4 threads/row, 8 floats (2 float4) per thread per matrix
    const int srow = tid >> 2;             // 0..127
    const int scb  = (tid & 3) * 8;        // float col base
    const float* pA = x  + (size_t)__ldg(fg + m0 + srow) * HDIM + scb;
    const float* pG = Wg + (size_t)(n0 + srow) * HDIM + scb;
    const float* pU = Wu + (size_t)(n0 + srow) * HDIM + scb;
    const int sts = srow * ROWB + (tid & 3) * 16;   // byte offset of hi

    // ldmatrix lane geometry
    const int laneRow = ((lane >> 3) & 1) * 8 + (lane & 7);
    const int laneK   = (lane >> 4) * 16;
    const int R       = 32 * (wid & 3);
    const int Cb      = 64 * ((wid >> 2) & 1);
    const int bSec    = (wid >= 8) ? K1_BUHI : K1_BGHI;

    float acc[2][8][4];
#pragma unroll
    for (int f = 0; f < 2; f++)
#pragma unroll
        for (int n = 0; n < 8; n++)
#pragma unroll
            for (int q = 0; q < 4; q++) acc[f][n][q] = 0.f;

    // prologue: chunk 0 -> buf 0
    float4 rA0 = *reinterpret_cast<const float4*>(pA);
    float4 rA1 = *reinterpret_cast<const float4*>(pA + 4);
    float4 rG0 = *reinterpret_cast<const float4*>(pG);
    float4 rG1 = *reinterpret_cast<const float4*>(pG + 4);
    float4 rU0 = *reinterpret_cast<const float4*>(pU);
    float4 rU1 = *reinterpret_cast<const float4*>(pU + 4);
    split_store(sm + sts,               sm + K1_ALO  + sts,     rA0);
    split_store(sm + sts + 8,           sm + K1_ALO  + sts + 8, rA1);
    split_store(sm + K1_BGHI + sts,     sm + K1_BGLO + sts,     rG0);
    split_store(sm + K1_BGHI + sts + 8, sm + K1_BGLO + sts + 8, rG1);
    split_store(sm + K1_BUHI + sts,     sm + K1_BULO + sts,     rU0);
    split_store(sm + K1_BUHI + sts + 8, sm + K1_BULO + sts + 8, rU1);

#pragma unroll 1
    for (int c = 0; c < NC1; c++) {
        __syncthreads();
        if (c + 1 < NC1) {
            const int k0 = (c + 1) * 32;
            rA0 = *reinterpret_cast<const float4*>(pA + k0);
            rA1 = *reinterpret_cast<const float4*>(pA + k0 + 4);
            rG0 = *reinterpret_cast<const float4*>(pG + k0);
            rG1 = *reinterpret_cast<const float4*>(pG + k0 + 4);
            rU0 = *reinterpret_cast<const float4*>(pU + k0);
            rU1 = *reinterpret_cast<const float4*>(pU + k0 + 4);
        }
        const uint32_t sb = smb + (uint32_t)(c & 1) * STAGE1;
#pragma unroll
        for (int s = 0; s < 2; s++) {
            const uint32_t ab = sb + (uint32_t)((R + laneRow) * ROWB + laneK + 32 * s);
            uint32_t ah[2][4], al[2][4];
            ldsm4(ab,                      ah[0][0], ah[0][1], ah[0][2], ah[0][3]);
            ldsm4(ab + 16 * ROWB,          ah[1][0], ah[1][1], ah[1][2], ah[1][3]);
            ldsm4(ab + K1_ALO,             al[0][0], al[0][1], al[0][2], al[0][3]);
            ldsm4(ab + K1_ALO + 16 * ROWB, al[1][0], al[1][1], al[1][2], al[1][3]);
#pragma unroll
            for (int gp = 0; gp < 4; gp++) {
                const uint32_t bb = sb + (uint32_t)(bSec +
                    (Cb + 16 * gp + laneRow) * ROWB + laneK + 32 * s);
                uint32_t bh[4], bl[4];
                ldsm4(bb,         bh[0], bh[1], bh[2], bh[3]);
                ldsm4(bb + 10240, bl[0], bl[1], bl[2], bl[3]);
#pragma unroll
                for (int f = 0; f < 2; f++)
#pragma unroll
                    for (int h = 0; h < 2; h++) {
                        float* cc = acc[f][2 * gp + h];
                        hmma(cc, ah[f], bh[h], bh[2 + h]);
                        hmma(cc, ah[f], bl[h], bl[2 + h]);
                        hmma(cc, al[f], bh[h], bh[2 + h]);
                    }
            }
        }
        if (c + 1 < NC1) {
            char* nb = sm + (size_t)((c + 1) & 1) * STAGE1;
            split_store(nb + sts,               nb + K1_ALO  + sts,     rA0);
            split_store(nb + sts + 8,           nb + K1_ALO  + sts + 8, rA1);
            split_store(nb + K1_BGHI + sts,     nb + K1_BGLO + sts,     rG0);
            split_store(nb + K1_BGHI + sts + 8, nb + K1_BGLO + sts + 8, rG1);
            split_store(nb + K1_BUHI + sts,     nb + K1_BULO + sts,     rU0);
            split_store(nb + K1_BUHI + sts + 8, nb + K1_BULO + sts + 8, rU1);
        }
    }

    // ---- epilogue: up warps park in smem; gate warps combine ----
    __syncthreads();
    float* upbuf = reinterpret_cast<float*>(sm);  // 8 warps x 32 x 68 floats
    if (wid >= 8) {
        const int w = wid - 8;
#pragma unroll
        for (int f = 0; f < 2; f++)
#pragma unroll
            for (int n = 0; n < 8; n++) {
                int row = 16 * f + (lane >> 2);
                int col = 8 * n + (lane & 3) * 2;
                float* b0 = upbuf + w * 2176 + row * 68 + col;
                b0[0] = acc[f][n][0]; b0[1] = acc[f][n][1];
                float* b1 = b0 + 8 * 68;
                b1[0] = acc[f][n][2]; b1[1] = acc[f][n][3];
            }
    }
    __syncthreads();
    if (wid < 8) {
        const int w = wid;
#pragma unroll
        for (int f = 0; f < 2; f++)
#pragma unroll
            for (int n = 0; n < 8; n++) {
                int row = 16 * f + (lane >> 2);
                int col = 8 * n + (lane & 3) * 2;
                const float* b0 = upbuf + w * 2176 + row * 68 + col;
                const float* b1 = b0 + 8 * 68;
                float* o0 = g_h + (size_t)(m0 + R + row) * IDIM + n0 + Cb + col;
                float* o1 = o0 + (size_t)8 * IDIM;
                *reinterpret_cast<float2*>(o0) =
                    make_float2(silu(acc[f][n][0]) * b0[0],
                                silu(acc[f][n][1]) * b0[1]);
                *reinterpret_cast<float2*>(o1) =
                    make_float2(silu(acc[f][n][2]) * b1[0],
                                silu(acc[f][n][3]) * b1[1]);
            }
    }
}

// ---------------------------------------------------------------------------
// Kernel 2: down projection, 512 threads, CTA tile 256m x 128n.
// 16 warps: 8m x 2n of 32x64 warp tiles. Same R3 data path.
// ---------------------------------------------------------------------------
__global__ __launch_bounds__(512, 1)
void k2_down(const float* __restrict__ Wd)
{
    extern __shared__ __align__(128) char sm[];
    const uint32_t smb = smem_u32(sm);
    const int tid  = threadIdx.x;
    const int wid  = tid >> 5;
    const int lane = tid & 31;
    const int m0 = blockIdx.x * 256;   // m fastest
    const int n0 = blockIdx.y * 128;

    // A staging: 2 threads/row (256 rows), 16 floats (4 float4) per thread
    const int arow = tid >> 1;
    const int acb  = (tid & 1) * 16;
    const float* pA = g_h + (size_t)(m0 + arow) * IDIM + acb;
    const int stsA = arow * ROWB + (tid & 1) * 32;
    // B staging: 4 threads/row (128 rows), 8 floats (2 float4) per thread
    const int brow = tid >> 2;
    const int bcb  = (tid & 3) * 8;
    const float* pB = Wd + (size_t)(n0 + brow) * IDIM + bcb;
    const int stsB = brow * ROWB + (tid & 3) * 16;

    const int laneRow = ((lane >> 3) & 1) * 8 + (lane & 7);
    const int laneK   = (lane >> 4) * 16;
    const int R       = 32 * (wid & 7);
    const int Cb      = 64 * (wid >> 3);

    float acc[2][8][4];
#pragma unroll
    for (int f = 0; f < 2; f++)
#pragma unroll
        for (int n = 0; n < 8; n++)
#pragma unroll
            for (int q = 0; q < 4; q++) acc[f][n][q] = 0.f;

    float4 rA0 = *reinterpret_cast<const float4*>(pA);
    float4 rA1 = *reinterpret_cast<const float4*>(pA + 4);
    float4 rA2 = *reinterpret_cast<const float4*>(pA + 8);
    float4 rA3 = *reinterpret_cast<const float4*>(pA + 12);
    float4 rB0 = *reinterpret_cast<const float4*>(pB);
    float4 rB1 = *reinterpret_cast<const float4*>(pB + 4);
    split_store(sm + stsA,                sm + K2_ALO + stsA,      rA0);
    split_store(sm + stsA + 8,            sm + K2_ALO + stsA + 8,  rA1);
    split_store(sm + stsA + 16,           sm + K2_ALO + stsA + 16, rA2);
    split_store(sm + stsA + 24,           sm + K2_ALO + stsA + 24, rA3);
    split_store(sm + K2_BHI + stsB,       sm + K2_BLO + stsB,      rB0);
    split_store(sm + K2_BHI + stsB + 8,   sm + K2_BLO + stsB + 8,  rB1);

#pragma unroll 1
    for (int c = 0; c < NC2; c++) {
        __syncthreads();
        if (c + 1 < NC2) {
            const int k0 = (c + 1) * 32;
            rA0 = *reinterpret_cast<const float4*>(pA + k0);
            rA1 = *reinterpret_cast<const float4*>(pA + k0 + 4);
            rA2 = *reinterpret_cast<const float4*>(pA + k0 + 8);
            rA3 = *reinterpret_cast<const float4*>(pA + k0 + 12);
            rB0 = *reinterpret_cast<const float4*>(pB + k0);
            rB1 = *reinterpret_cast<const float4*>(pB + k0 + 4);
        }
        const uint32_t sb = smb + (uint32_t)(c & 1) * STAGE2;
#pragma unroll
        for (int s = 0; s < 2; s++) {
            const uint32_t ab = sb + (uint32_t)((R + laneRow) * ROWB + laneK + 32 * s);
            uint32_t ah[2][4], al[2][4];
            ldsm4(ab,                      ah[0][0], ah[0][1], ah[0][2], ah[0][3]);
            ldsm4(ab + 16 * ROWB,          ah[1][0], ah[1][1], ah[1][2], ah[1][3]);
            ldsm4(ab + K2_ALO,             al[0][0], al[0][1], al[0][2], al[0][3]);
            ldsm4(ab + K2_ALO + 16 * ROWB, al[1][0], al[1][1], al[1][2], al[1][3]);
#pragma unroll
            for (int gp = 0; gp < 4; gp++) {
                const uint32_t bb = sb + (uint32_t)(K2_BHI +
                    (Cb + 16 * gp + laneRow) * ROWB + laneK + 32 * s);
                uint32_t bh[4], bl[4];
                ldsm4(bb,         bh[0], bh[1], bh[2], bh[3]);
                ldsm4(bb + 10240, bl[0], bl[1], bl[2], bl[3]);
#pragma unroll
                for (int f = 0; f < 2; f++)
#pragma unroll
                    for (int h = 0; h < 2; h++) {
                        float* cc = acc[f][2 * gp + h];
                        hmma(cc, ah[f], bh[h], bh[2 + h]);
                        hmma(cc, ah[f], bl[h], bl[2 + h]);
                        hmma(cc, al[f], bh[h], bh[2 + h]);
                    }
            }
        }
        if (c + 1 < NC2) {
            char* nb = sm + (size_t)((c + 1) & 1) * STAGE2;
            split_store(nb + stsA,              nb + K2_ALO + stsA,      rA0);
            split_store(nb + stsA + 8,          nb + K2_ALO + stsA + 8,  rA1);
            split_store(nb + stsA + 16,         nb + K2_ALO + stsA + 16, rA2);
            split_store(nb + stsA + 24,         nb + K2_ALO + stsA + 24, rA3);
            split_store(nb + K2_BHI + stsB,     nb + K2_BLO + stsB,      rB0);
            split_store(nb + K2_BHI + stsB + 8, nb + K2_BLO + stsB + 8,  rB1);
        }
    }

    // epilogue: direct fp32 stores
#pragma unroll
    for (int f = 0; f < 2; f++)
#pragma unroll
        for (int n = 0; n < 8; n++) {
            int row = m0 + R + 16 * f + (lane >> 2);
            int col = n0 + Cb + 8 * n + (lane & 3) * 2;
            float* o0 = g_down + (size_t)row * HDIM + col;
            float* o1 = o0 + (size_t)8 * HDIM;
            *reinterpret_cast<float2*>(o0) = make_float2(acc[f][n][0], acc[f][n][1]);
            *reinterpret_cast<float2*>(o1) = make_float2(acc[f][n][2], acc[f][n][3]);
        }
}

// ---------------------------------------------------------------------------
// Kernel 3: scatter
// ---------------------------------------------------------------------------
__global__ __launch_bounds__(256)
void scatter_kernel(const int* __restrict__ scatter_indices,
                    float* __restrict__ out)
{
    const int t = blockIdx.x;
    const int c = scatter_indices[t];
    const float4* src = reinterpret_cast<const float4*>(g_down + (size_t)c * HDIM);
    float4*       dst = reinterpret_cast<float4*>(out + (size_t)t * HDIM);
#pragma unroll
    for (int j = threadIdx.x; j < HDIM / 4; j += 256)
        dst[j] = src[j];
}

// ---------------------------------------------------------------------------
extern "C" void kernel_launch(void* const* d_in, const int* in_sizes, int n_in,
                              void* d_out, int out_size)
{
    const float* x  = (const float*)d_in[0];
    const float* Wg = (const float*)d_in[1];
    const float* Wu = (const float*)d_in[2];
    const float* Wd = (const float*)d_in[3];
    const int*   fg = (const int*)d_in[4];
    const int*   sc = (const int*)d_in[5];
    float*       out = (float*)d_out;

    cudaFuncSetAttribute(k1_gateup, cudaFuncAttributeMaxDynamicSharedMemorySize, SMEM1);
    cudaFuncSetAttribute(k2_down,   cudaFuncAttributeMaxDynamicSharedMemorySize, SMEM2);

    dim3 g1(CDIM / 128, IDIM / 128);   // (64 m fastest, 64 n)
    k1_gateup<<<g1, 512, SMEM1>>>(x, Wg, Wu, fg);

    dim3 g2(CDIM / 256, HDIM / 128);   // (32 m fastest, 16 n)
    k2_down<<<g2, 512, SMEM2>>>(Wd);

    scatter_kernel<<<NTOK, 256>>>(sc, out);
}